// round 13
// baseline (speedup 1.0000x reference)
#include <cuda_runtime.h>
#include <cuda_fp16.h>
#include <cuda_bf16.h>
#include <cstdint>

static constexpr int IN_F=4096, OUT_F=4096;
static constexpr int BM=256, BN=128, BK=64, STAGES=3;
static constexpr int A_ST=BM*BK*2, B_ST=BN*BK*2, STAGE_B=A_ST+B_ST;  // 48K
static constexpr int SMEM_DYN=STAGES*STAGE_B;                        // 147456

__device__ __align__(128) __half g_wh[(size_t)OUT_F*IN_F];
__device__ __align__(128) __half g_xh[(size_t)8192*IN_F];
__device__ int g_mpk, g_mv;

#define DI __device__ __forceinline__
DI uint32_t s2u(const void* p){uint32_t a;
  asm("{ .reg .u64 t; cvta.to.shared.u64 t, %1; cvt.u32.u64 %0, t; }":"=r"(a):"l"(p));return a;}
DI void cpasync16(uint32_t d,const void* s){
  asm volatile("cp.async.cg.shared.global [%0], [%1], 16;"::"r"(d),"l"(s):"memory");}
DI void cp_commit(){asm volatile("cp.async.commit_group;":::"memory");}
template<int N> DI void cp_wait(){asm volatile("cp.async.wait_group %0;"::"n"(N):"memory");}
DI void ldm4(uint32_t* r,uint32_t a){
  asm volatile("ldmatrix.sync.aligned.m8n8.x4.shared.b16 {%0,%1,%2,%3}, [%4];"
    :"=r"(r[0]),"=r"(r[1]),"=r"(r[2]),"=r"(r[3]):"r"(a));}
DI void mma16816(float* d,const uint32_t* a,const uint32_t* b){
  asm volatile("mma.sync.aligned.m16n8k16.row.col.f32.f16.f16.f32 "
    "{%0,%1,%2,%3},{%4,%5,%6,%7},{%8,%9},{%0,%1,%2,%3};"
    :"+f"(d[0]),"+f"(d[1]),"+f"(d[2]),"+f"(d[3])
    :"r"(a[0]),"r"(a[1]),"r"(a[2]),"r"(a[3]),"r"(b[0]),"r"(b[1]));}

// dtype detection (harness promotes uint8->int32/fp32, fp16->bf16/fp32)
__global__ void k_detect(const uint32_t* pk, const uint32_t* vals){
  if(threadIdx.x|blockIdx.x) return;
  int lt=0, fl=0;
  for(int i=0;i<32;i++){uint32_t w=pk[i]; if(w<256u)lt++;
    uint32_t e=(w>>23)&0xFF; if(w==0u||(e>=126&&e<=135))fl++;}
  g_mpk = (fl>=30)?2:(lt>=30?1:0);
  int hb=0, lb=0, nz=0;
  for(int i=0;i<64;i++){uint32_t w=vals[i]; if(!w)continue; nz++;
    uint32_t eh=(w>>23)&0xFF, el=(w>>7)&0xFF;
    if(eh>=90&&eh<127)hb++; if(el>=90&&el<127)lb++;}
  g_mv = (nz&&lb*2>=nz)?1:((nz&&hb*2>=nz)?2:0);
}

__global__ void k_dequant(const void* pkv, const float* sc){
  constexpr int W32=IN_F/8;
  int i=blockIdx.x*blockDim.x+threadIdx.x; if(i>=OUT_F*W32)return;
  int r=i>>9, c=i&(W32-1), m=g_mpk;
  uint32_t v;
  if(m==0) v=((const uint32_t*)pkv)[(size_t)r*W32+c];
  else if(m==1){const int32_t* p=(const int32_t*)pkv+(size_t)r*(IN_F/2)+c*4;
    v=(uint32_t)(p[0]&0xFF)|((uint32_t)(p[1]&0xFF)<<8)|
      ((uint32_t)(p[2]&0xFF)<<16)|((uint32_t)(p[3]&0xFF)<<24);}
  else {const float* p=(const float*)pkv+(size_t)r*(IN_F/2)+c*4;
    v=(uint32_t)(int)p[0]|((uint32_t)(int)p[1]<<8)|
      ((uint32_t)(int)p[2]<<16)|((uint32_t)(int)p[3]<<24);}
  float s=sc[r], f[8];
#pragma unroll
  for(int j=0;j<8;j++) f[j]=(float)((int)((v>>(4*j))&0xF)-8)*s;
  __half2 h0=__floats2half2_rn(f[0],f[1]), h1=__floats2half2_rn(f[2],f[3]);
  __half2 h2=__floats2half2_rn(f[4],f[5]), h3=__floats2half2_rn(f[6],f[7]);
  uint4 o={*(uint32_t*)&h0,*(uint32_t*)&h1,*(uint32_t*)&h2,*(uint32_t*)&h3};
  *reinterpret_cast<uint4*>(g_wh+(size_t)r*IN_F+(size_t)c*8)=o;
}

__global__ void k_csr(const void* vv, const int* cols, const int* ptr, const float* alpha){
  int r=blockIdx.x*(blockDim.x>>5)+(threadIdx.x>>5); if(r>=OUT_F)return;
  int lane=threadIdx.x&31, e=ptr[r+1], m=g_mv;
  float a=*alpha;
  __half* w=g_wh+(size_t)r*IN_F;
  for(int j=ptr[r]+lane;j<e;j+=32){
    float v = (m==0)? __half2float(((const __half*)vv)[j])
            : (m==1)? __bfloat162float(((const __nv_bfloat16*)vv)[j])
            : ((const float*)vv)[j];
    int c=cols[j];
    w[c]=__float2half(__half2float(w[c])+a*v);
  }
}

__global__ void k_xh(const float4* __restrict__ x, int n8){
  int i=blockIdx.x*blockDim.x+threadIdx.x; if(i>=n8)return;
  float4 v0=x[2*i], v1=x[2*i+1];
  __half2 h0=__floats2half2_rn(v0.x,v0.y), h1=__floats2half2_rn(v0.z,v0.w);
  __half2 h2=__floats2half2_rn(v1.x,v1.y), h3=__floats2half2_rn(v1.z,v1.w);
  uint4 o={*(uint32_t*)&h0,*(uint32_t*)&h1,*(uint32_t*)&h2,*(uint32_t*)&h3};
  *reinterpret_cast<uint4*>(g_xh+(size_t)i*8)=o;
}

// out[M,OUT_F] = Xh[M,K]*Wh[OUT_F,K]^T ; CTA 256x128 @512thr, warp 64x32, 16 warps/SM
__global__ void __launch_bounds__(512, 1)
k_gemm(const __half* __restrict__ X, const __half* __restrict__ W, float* __restrict__ out){
  extern __shared__ char smem[];
  uint32_t sb=s2u(smem);
  const int tid=threadIdx.x, wid=tid>>5, L=tid&31;
  const int wm=wid>>2, wn=wid&3;                      // 4 x 4 warps
  const int m_base=blockIdx.y*BM, n_base=blockIdx.x*BN;
  const __half* gA=X+(size_t)m_base*IN_F;
  const __half* gW=W+(size_t)n_base*IN_F;
  const int arow=wm*64+(L&15), a_hi=L>>4;             // mt (0..3) adds 16
  const int brow=wn*32+(L>>4)*8+(L&7), b_hi=(L>>3)&1; // p (0..1) adds 16
  float acc[4][4][4];
#pragma unroll
  for(int mt=0;mt<4;mt++)
#pragma unroll
    for(int nt=0;nt<4;nt++)
#pragma unroll
      for(int q=0;q<4;q++) acc[mt][nt][q]=0.f;
  constexpr int KT=IN_F/BK;                           // 64

#define LOAD_STAGE(kt,s) do{ \
    uint32_t b_=sb+(s)*STAGE_B; \
    const __half* ga_=gA+(size_t)(kt)*BK; \
    const __half* gb_=gW+(size_t)(kt)*BK; \
    _Pragma("unroll") for(int i_=0;i_<4;i_++){ \
      int ix_=tid+i_*512, r_=ix_>>3, c_=ix_&7; \
      cpasync16(b_+r_*128+((c_^(r_&7))<<4), ga_+(size_t)r_*IN_F+c_*8);} \
    _Pragma("unroll") for(int i_=0;i_<2;i_++){ \
      int ix_=tid+i_*512, r_=ix_>>3, c_=ix_&7; \
      cpasync16(b_+A_ST+r_*128+((c_^(r_&7))<<4), gb_+(size_t)r_*IN_F+c_*8);} \
  }while(0)

#pragma unroll
  for(int s=0;s<STAGES-1;s++){ LOAD_STAGE(s,s); cp_commit(); }

  for(int kt=0;kt<KT;kt++){
    cp_wait<STAGES-2>();
    __syncthreads();
    int cs=kt%STAGES;
    uint32_t base=sb+cs*STAGE_B;
    if(kt+STAGES-1<KT) LOAD_STAGE(kt+STAGES-1,(kt+STAGES-1)%STAGES);
    cp_commit();
#pragma unroll
    for(int ks=0;ks<4;ks++){
      uint32_t a[4][4], b[2][4];
#pragma unroll
      for(int mt=0;mt<4;mt++){
        int row=arow+mt*16, c=ks*2+a_hi;
        ldm4(a[mt], base+row*128+((c^(row&7))<<4));
      }
#pragma unroll
      for(int p=0;p<2;p++){
        int row=brow+p*16, c=ks*2+b_hi;
        ldm4(b[p], base+A_ST+row*128+((c^(row&7))<<4));
      }
#pragma unroll
      for(int mt=0;mt<4;mt++)
#pragma unroll
        for(int nt=0;nt<4;nt++)
          mma16816(acc[mt][nt], a[mt], b[nt>>1]+(nt&1)*2);
    }
  }
  const int gid=L>>2, tig=L&3;
#pragma unroll
  for(int mt=0;mt<4;mt++)
#pragma unroll
    for(int nt=0;nt<4;nt++){
      int r0=m_base+wm*64+mt*16+gid;
      int c0=n_base+wn*32+nt*8+tig*2;
      float2 v0={acc[mt][nt][0],acc[mt][nt][1]};
      float2 v1={acc[mt][nt][2],acc[mt][nt][3]};
      *reinterpret_cast<float2*>(out+(size_t)r0*OUT_F+c0)=v0;
      *reinterpret_cast<float2*>(out+(size_t)(r0+8)*OUT_F+c0)=v1;
    }
#undef LOAD_STAGE
}

extern "C" void kernel_launch(void* const* d_in, const int* in_sizes, int n_in,
                              void* d_out, int out_size){
  const float* x      =(const float*)d_in[0];
  const void*  packed =d_in[1];
  const float* scales =(const float*)d_in[2];
  const void*  vals   =d_in[3];
  const int*   cols   =(const int*)d_in[4];
  const int*   ptr    =(const int*)d_in[5];
  const float* alpha  =(const float*)d_in[6];
  const int M = in_sizes[0]/IN_F;

  cudaFuncSetAttribute(k_gemm, cudaFuncAttributeMaxDynamicSharedMemorySize, SMEM_DYN);

  k_detect<<<1,1>>>((const uint32_t*)packed,(const uint32_t*)vals);
  k_dequant<<<(OUT_F*(IN_F/8)+255)/256,256>>>(packed, scales);
  k_csr<<<OUT_F/8,256>>>(vals, cols, ptr, alpha);
  int n8=M*IN_F/8;
  k_xh<<<(n8+255)/256,256>>>((const float4*)x, n8);

  void *wp=nullptr,*xp=nullptr;
  cudaGetSymbolAddress(&wp,g_wh);
  cudaGetSymbolAddress(&xp,g_xh);
  dim3 grid(OUT_F/BN, M/BM);
  k_gemm<<<grid,512,SMEM_DYN>>>((const __half*)xp,(const __half*)wp,(float*)d_out);
}

// round 14
// speedup vs baseline: 1.0353x; 1.0353x over previous
#include <cuda_runtime.h>
#include <cuda_fp16.h>
#include <cuda_bf16.h>
#include <cstdint>

static constexpr int IN_F=4096, OUT_F=4096;
static constexpr int BM=256, BN=128, BK=64, STAGES=4;
static constexpr int A_ST=BM*BK*2, B_ST=BN*BK*2, STAGE_B=A_ST+B_ST;  // 48K
static constexpr int SMEM_DYN=STAGES*STAGE_B;                        // 196608

__device__ __align__(128) __half g_wh[(size_t)OUT_F*IN_F];
__device__ __align__(128) __half g_xh[(size_t)8192*IN_F];

#define DI __device__ __forceinline__
DI uint32_t s2u(const void* p){uint32_t a;
  asm("{ .reg .u64 t; cvta.to.shared.u64 t, %1; cvt.u32.u64 %0, t; }":"=r"(a):"l"(p));return a;}
DI void cpasync16(uint32_t d,const void* s){
  asm volatile("cp.async.cg.shared.global [%0], [%1], 16;"::"r"(d),"l"(s):"memory");}
DI void cp_commit(){asm volatile("cp.async.commit_group;":::"memory");}
template<int N> DI void cp_wait(){asm volatile("cp.async.wait_group %0;"::"n"(N):"memory");}
DI void ldm4(uint32_t* r,uint32_t a){
  asm volatile("ldmatrix.sync.aligned.m8n8.x4.shared.b16 {%0,%1,%2,%3}, [%4];"
    :"=r"(r[0]),"=r"(r[1]),"=r"(r[2]),"=r"(r[3]):"r"(a));}
DI void mma16816(float* d,const uint32_t* a,const uint32_t* b){
  asm volatile("mma.sync.aligned.m16n8k16.row.col.f32.f16.f16.f32 "
    "{%0,%1,%2,%3},{%4,%5,%6,%7},{%8,%9},{%0,%1,%2,%3};"
    :"+f"(d[0]),"+f"(d[1]),"+f"(d[2]),"+f"(d[3])
    :"r"(a[0]),"r"(a[1]),"r"(a[2]),"r"(a[3]),"r"(b[0]),"r"(b[1]));}

// ---- fused preprocessing: W dequant + CSR patch (blocks 0..511) and x->fp16 (rest)
// Per-block dtype re-detection (harness may promote uint8->int32/fp32, fp16->bf16/fp32).
__global__ void __launch_bounds__(256)
k_pre(const float* __restrict__ x, const void* __restrict__ pkv,
      const float* __restrict__ sc, const void* __restrict__ vv,
      const int* __restrict__ cols, const int* __restrict__ ptr,
      const float* __restrict__ alpha)
{
  const int tid=threadIdx.x, b=blockIdx.x;
  if(b < 512){
    __shared__ int s_mpk, s_mv;
    if(tid==0){
      const uint32_t* pk=(const uint32_t*)pkv;
      const uint32_t* vals=(const uint32_t*)vv;
      int lt=0, fl=0;
      for(int i=0;i<32;i++){uint32_t w=pk[i]; if(w<256u)lt++;
        uint32_t e=(w>>23)&0xFF; if(w==0u||(e>=126&&e<=135))fl++;}
      s_mpk=(fl>=30)?2:(lt>=30?1:0);
      int hb=0, lb=0, nz=0;
      for(int i=0;i<64;i++){uint32_t w=vals[i]; if(!w)continue; nz++;
        uint32_t eh=(w>>23)&0xFF, el=(w>>7)&0xFF;
        if(eh>=90&&eh<127)hb++; if(el>=90&&el<127)lb++;}
      s_mv=(nz&&lb*2>=nz)?1:((nz&&hb*2>=nz)?2:0);
    }
    __syncthreads();
    const int mpk=s_mpk, mv=s_mv;
    const int r0=b*8;
    constexpr int W32=IN_F/8;   // 512 words/row
    // dequant 8 rows
#pragma unroll
    for(int j=0;j<16;j++){
      int idx=tid+j*256;               // 0..4095
      int r=r0+(idx>>9), c=idx&(W32-1);
      uint32_t v;
      if(mpk==0) v=((const uint32_t*)pkv)[(size_t)r*W32+c];
      else if(mpk==1){const int32_t* p=(const int32_t*)pkv+(size_t)r*(IN_F/2)+c*4;
        v=(uint32_t)(p[0]&0xFF)|((uint32_t)(p[1]&0xFF)<<8)|
          ((uint32_t)(p[2]&0xFF)<<16)|((uint32_t)(p[3]&0xFF)<<24);}
      else {const float* p=(const float*)pkv+(size_t)r*(IN_F/2)+c*4;
        v=(uint32_t)(int)p[0]|((uint32_t)(int)p[1]<<8)|
          ((uint32_t)(int)p[2]<<16)|((uint32_t)(int)p[3]<<24);}
      float s=sc[r], f[8];
#pragma unroll
      for(int k=0;k<8;k++) f[k]=(float)((int)((v>>(4*k))&0xF)-8)*s;
      __half2 h0=__floats2half2_rn(f[0],f[1]), h1=__floats2half2_rn(f[2],f[3]);
      __half2 h2=__floats2half2_rn(f[4],f[5]), h3=__floats2half2_rn(f[6],f[7]);
      uint4 o={*(uint32_t*)&h0,*(uint32_t*)&h1,*(uint32_t*)&h2,*(uint32_t*)&h3};
      *reinterpret_cast<uint4*>(g_wh+(size_t)r*IN_F+(size_t)c*8)=o;
    }
    __syncthreads();
    // CSR patch: warp w -> row r0+w
    {
      int r=r0+(tid>>5), lane=tid&31;
      float a=*alpha;
      int e=ptr[r+1];
      __half* w=g_wh+(size_t)r*IN_F;
      for(int j=ptr[r]+lane;j<e;j+=32){
        float v = (mv==0)? __half2float(((const __half*)vv)[j])
                : (mv==1)? __bfloat162float(((const __nv_bfloat16*)vv)[j])
                : ((const float*)vv)[j];
        int c=cols[j];
        w[c]=__float2half(__half2float(w[c])+a*v);
      }
    }
  } else {
    // x -> fp16 : each thread converts 8 floats
    int i=(b-512)*256+tid;              // i < M*IN_F/8
    const float4* xp=(const float4*)x;
    float4 v0=xp[2*i], v1=xp[2*i+1];
    __half2 h0=__floats2half2_rn(v0.x,v0.y), h1=__floats2half2_rn(v0.z,v0.w);
    __half2 h2=__floats2half2_rn(v1.x,v1.y), h3=__floats2half2_rn(v1.z,v1.w);
    uint4 o={*(uint32_t*)&h0,*(uint32_t*)&h1,*(uint32_t*)&h2,*(uint32_t*)&h3};
    *reinterpret_cast<uint4*>(g_xh+(size_t)i*8)=o;
  }
}

// ---- GEMM: out[M,OUT_F] = Xh[M,K]*Wh[OUT_F,K]^T ; CTA 256x128 @256thr, warp 64x64
__global__ void __launch_bounds__(256, 1)
k_gemm(const __half* __restrict__ X, const __half* __restrict__ W, float* __restrict__ out){
  extern __shared__ char smem[];
  uint32_t sb=s2u(smem);
  const int tid=threadIdx.x, wid=tid>>5, L=tid&31;
  const int wm=wid>>1, wn=wid&1;                    // 4 x 2 warps
  const int m_base=blockIdx.y*BM, n_base=blockIdx.x*BN;
  const __half* gA=X+(size_t)m_base*IN_F;
  const __half* gW=W+(size_t)n_base*IN_F;
  const int arow=wm*64+(L&15), a_hi=L>>4;           // mt (0..3) adds 16
  const int brow=wn*64+(L>>4)*8+(L&7), b_hi=(L>>3)&1; // p (0..3) adds 16
  float acc[4][8][4];
#pragma unroll
  for(int mt=0;mt<4;mt++)
#pragma unroll
    for(int nt=0;nt<8;nt++)
#pragma unroll
      for(int q=0;q<4;q++) acc[mt][nt][q]=0.f;
  constexpr int KT=IN_F/BK;                         // 64

#define LOAD_STAGE(kt,s) do{ \
    uint32_t b_=sb+(s)*STAGE_B; \
    const __half* ga_=gA+(size_t)(kt)*BK; \
    const __half* gb_=gW+(size_t)(kt)*BK; \
    _Pragma("unroll") for(int i_=0;i_<8;i_++){ \
      int ix_=tid+i_*256, r_=ix_>>3, c_=ix_&7; \
      cpasync16(b_+r_*128+((c_^(r_&7))<<4), ga_+(size_t)r_*IN_F+c_*8);} \
    _Pragma("unroll") for(int i_=0;i_<4;i_++){ \
      int ix_=tid+i_*256, r_=ix_>>3, c_=ix_&7; \
      cpasync16(b_+A_ST+r_*128+((c_^(r_&7))<<4), gb_+(size_t)r_*IN_F+c_*8);} \
  }while(0)

#pragma unroll
  for(int s=0;s<STAGES-1;s++){ LOAD_STAGE(s,s); cp_commit(); }

  for(int kt=0;kt<KT;kt++){
    cp_wait<STAGES-2>();
    __syncthreads();
    uint32_t base=sb+(kt&3)*STAGE_B;
    if(kt+STAGES-1<KT) LOAD_STAGE(kt+STAGES-1,(kt+STAGES-1)&3);
    cp_commit();
#pragma unroll
    for(int ks=0;ks<4;ks++){
      uint32_t a[4][4], b[4][4];
#pragma unroll
      for(int mt=0;mt<4;mt++){
        int row=arow+mt*16, c=ks*2+a_hi;
        ldm4(a[mt], base+row*128+((c^(row&7))<<4));
      }
#pragma unroll
      for(int p=0;p<4;p++){
        int row=brow+p*16, c=ks*2+b_hi;
        ldm4(b[p], base+A_ST+row*128+((c^(row&7))<<4));
      }
#pragma unroll
      for(int mt=0;mt<4;mt++)
#pragma unroll
        for(int nt=0;nt<8;nt++)
          mma16816(acc[mt][nt], a[mt], b[nt>>1]+(nt&1)*2);
    }
  }
  const int gid=L>>2, tig=L&3;
#pragma unroll
  for(int mt=0;mt<4;mt++)
#pragma unroll
    for(int nt=0;nt<8;nt++){
      int r0=m_base+wm*64+mt*16+gid;
      int c0=n_base+wn*64+nt*8+tig*2;
      float2 v0={acc[mt][nt][0],acc[mt][nt][1]};
      float2 v1={acc[mt][nt][2],acc[mt][nt][3]};
      *reinterpret_cast<float2*>(out+(size_t)r0*OUT_F+c0)=v0;
      *reinterpret_cast<float2*>(out+(size_t)(r0+8)*OUT_F+c0)=v1;
    }
#undef LOAD_STAGE
}

extern "C" void kernel_launch(void* const* d_in, const int* in_sizes, int n_in,
                              void* d_out, int out_size){
  const float* x      =(const float*)d_in[0];
  const void*  packed =d_in[1];
  const float* scales =(const float*)d_in[2];
  const void*  vals   =d_in[3];
  const int*   cols   =(const int*)d_in[4];
  const int*   ptr    =(const int*)d_in[5];
  const float* alpha  =(const float*)d_in[6];
  const int M = in_sizes[0]/IN_F;

  cudaFuncSetAttribute(k_gemm, cudaFuncAttributeMaxDynamicSharedMemorySize, SMEM_DYN);

  int nx_blocks = (M*IN_F/8)/256;     // 16384 for M=8192
  k_pre<<<512+nx_blocks,256>>>(x, packed, scales, vals, cols, ptr, alpha);

  void *wp=nullptr,*xp=nullptr;
  cudaGetSymbolAddress(&wp,g_wh);
  cudaGetSymbolAddress(&xp,g_xh);
  dim3 grid(OUT_F/BN, M/BM);
  k_gemm<<<grid,256,SMEM_DYN>>>((const __half*)xp,(const __half*)wp,(float*)d_out);
}

// round 15
// speedup vs baseline: 1.0915x; 1.0543x over previous
#include <cuda_runtime.h>
#include <cuda_fp16.h>
#include <cuda_bf16.h>
#include <cstdint>

static constexpr int IN_F=4096, OUT_F=4096;
static constexpr int BM=128, BN=128, BK=64, STAGES=3;
static constexpr int A_ST=BM*BK*2, B_ST=BN*BK*2, STAGE_B=A_ST+B_ST;  // 32K
static constexpr int SMEM_DYN=STAGES*STAGE_B;                        // 98304

__device__ __align__(128) __half g_wh[(size_t)OUT_F*IN_F];
__device__ __align__(128) __half g_xh[(size_t)8192*IN_F];

#define DI __device__ __forceinline__
DI uint32_t s2u(const void* p){uint32_t a;
  asm("{ .reg .u64 t; cvta.to.shared.u64 t, %1; cvt.u32.u64 %0, t; }":"=r"(a):"l"(p));return a;}
DI void cpasync16(uint32_t d,const void* s){
  asm volatile("cp.async.cg.shared.global [%0], [%1], 16;"::"r"(d),"l"(s):"memory");}
DI void cp_commit(){asm volatile("cp.async.commit_group;":::"memory");}
template<int N> DI void cp_wait(){asm volatile("cp.async.wait_group %0;"::"n"(N):"memory");}
DI void ldm4(uint32_t* r,uint32_t a){
  asm volatile("ldmatrix.sync.aligned.m8n8.x4.shared.b16 {%0,%1,%2,%3}, [%4];"
    :"=r"(r[0]),"=r"(r[1]),"=r"(r[2]),"=r"(r[3]):"r"(a));}
DI void mma16816(float* d,const uint32_t* a,const uint32_t* b){
  asm volatile("mma.sync.aligned.m16n8k16.row.col.f32.f16.f16.f32 "
    "{%0,%1,%2,%3},{%4,%5,%6,%7},{%8,%9},{%0,%1,%2,%3};"
    :"+f"(d[0]),"+f"(d[1]),"+f"(d[2]),"+f"(d[3])
    :"r"(a[0]),"r"(a[1]),"r"(a[2]),"r"(a[3]),"r"(b[0]),"r"(b[1]));}

// ---- fused preprocessing: W dequant + CSR patch (blocks 0..511) and x->fp16 (rest)
__global__ void __launch_bounds__(256)
k_pre(const float* __restrict__ x, const void* __restrict__ pkv,
      const float* __restrict__ sc, const void* __restrict__ vv,
      const int* __restrict__ cols, const int* __restrict__ ptr,
      const float* __restrict__ alpha)
{
  const int tid=threadIdx.x, b=blockIdx.x;
  if(b < 512){
    __shared__ int s_mpk, s_mv;
    if(tid==0){
      const uint32_t* pk=(const uint32_t*)pkv;
      const uint32_t* vals=(const uint32_t*)vv;
      int lt=0, fl=0;
      for(int i=0;i<32;i++){uint32_t w=pk[i]; if(w<256u)lt++;
        uint32_t e=(w>>23)&0xFF; if(w==0u||(e>=126&&e<=135))fl++;}
      s_mpk=(fl>=30)?2:(lt>=30?1:0);
      int hb=0, lb=0, nz=0;
      for(int i=0;i<64;i++){uint32_t w=vals[i]; if(!w)continue; nz++;
        uint32_t eh=(w>>23)&0xFF, el=(w>>7)&0xFF;
        if(eh>=90&&eh<127)hb++; if(el>=90&&el<127)lb++;}
      s_mv=(nz&&lb*2>=nz)?1:((nz&&hb*2>=nz)?2:0);
    }
    __syncthreads();
    const int mpk=s_mpk, mv=s_mv;
    const int r0=b*8;
    constexpr int W32=IN_F/8;
#pragma unroll
    for(int j=0;j<16;j++){
      int idx=tid+j*256;
      int r=r0+(idx>>9), c=idx&(W32-1);
      uint32_t v;
      if(mpk==0) v=((const uint32_t*)pkv)[(size_t)r*W32+c];
      else if(mpk==1){const int32_t* p=(const int32_t*)pkv+(size_t)r*(IN_F/2)+c*4;
        v=(uint32_t)(p[0]&0xFF)|((uint32_t)(p[1]&0xFF)<<8)|
          ((uint32_t)(p[2]&0xFF)<<16)|((uint32_t)(p[3]&0xFF)<<24);}
      else {const float* p=(const float*)pkv+(size_t)r*(IN_F/2)+c*4;
        v=(uint32_t)(int)p[0]|((uint32_t)(int)p[1]<<8)|
          ((uint32_t)(int)p[2]<<16)|((uint32_t)(int)p[3]<<24);}
      float s=sc[r], f[8];
#pragma unroll
      for(int k=0;k<8;k++) f[k]=(float)((int)((v>>(4*k))&0xF)-8)*s;
      __half2 h0=__floats2half2_rn(f[0],f[1]), h1=__floats2half2_rn(f[2],f[3]);
      __half2 h2=__floats2half2_rn(f[4],f[5]), h3=__floats2half2_rn(f[6],f[7]);
      uint4 o={*(uint32_t*)&h0,*(uint32_t*)&h1,*(uint32_t*)&h2,*(uint32_t*)&h3};
      *reinterpret_cast<uint4*>(g_wh+(size_t)r*IN_F+(size_t)c*8)=o;
    }
    __syncthreads();
    {
      int r=r0+(tid>>5), lane=tid&31;
      float a=*alpha;
      int e=ptr[r+1];
      __half* w=g_wh+(size_t)r*IN_F;
      for(int j=ptr[r]+lane;j<e;j+=32){
        float v = (mv==0)? __half2float(((const __half*)vv)[j])
                : (mv==1)? __bfloat162float(((const __nv_bfloat16*)vv)[j])
                : ((const float*)vv)[j];
        int c=cols[j];
        w[c]=__float2half(__half2float(w[c])+a*v);
      }
    }
  } else {
    int i=(b-512)*256+tid;
    const float4* xp=(const float4*)x;
    float4 v0=xp[2*i], v1=xp[2*i+1];
    __half2 h0=__floats2half2_rn(v0.x,v0.y), h1=__floats2half2_rn(v0.z,v0.w);
    __half2 h2=__floats2half2_rn(v1.x,v1.y), h3=__floats2half2_rn(v1.z,v1.w);
    uint4 o={*(uint32_t*)&h0,*(uint32_t*)&h1,*(uint32_t*)&h2,*(uint32_t*)&h3};
    *reinterpret_cast<uint4*>(g_xh+(size_t)i*8)=o;
  }
}

// ---- GEMM: CTA 128x128 @256thr, warp 32x64, 3 stages, 2 CTAs/SM for barrier overlap
__global__ void __launch_bounds__(256, 2)
k_gemm(const __half* __restrict__ X, const __half* __restrict__ W, float* __restrict__ out){
  extern __shared__ char smem[];
  uint32_t sb=s2u(smem);
  const int tid=threadIdx.x, wid=tid>>5, L=tid&31;
  const int wm=wid>>1, wn=wid&1;                      // 4 x 2 warps
  const int m_base=blockIdx.y*BM, n_base=blockIdx.x*BN;
  const __half* gA=X+(size_t)m_base*IN_F;
  const __half* gW=W+(size_t)n_base*IN_F;
  const int arow=wm*32+(L&15), a_hi=L>>4;             // mt (0..1) adds 16
  const int brow=wn*64+(L>>4)*8+(L&7), b_hi=(L>>3)&1; // p (0..3) adds 16
  float acc[2][8][4];
#pragma unroll
  for(int mt=0;mt<2;mt++)
#pragma unroll
    for(int nt=0;nt<8;nt++)
#pragma unroll
      for(int q=0;q<4;q++) acc[mt][nt][q]=0.f;
  constexpr int KT=IN_F/BK;                           // 64

#define LOAD_STAGE(kt,s) do{ \
    uint32_t b_=sb+(s)*STAGE_B; \
    const __half* ga_=gA+(size_t)(kt)*BK; \
    const __half* gb_=gW+(size_t)(kt)*BK; \
    _Pragma("unroll") for(int i_=0;i_<4;i_++){ \
      int ix_=tid+i_*256, r_=ix_>>3, c_=ix_&7; \
      cpasync16(b_+r_*128+((c_^(r_&7))<<4), ga_+(size_t)r_*IN_F+c_*8);} \
    _Pragma("unroll") for(int i_=0;i_<4;i_++){ \
      int ix_=tid+i_*256, r_=ix_>>3, c_=ix_&7; \
      cpasync16(b_+A_ST+r_*128+((c_^(r_&7))<<4), gb_+(size_t)r_*IN_F+c_*8);} \
  }while(0)

#pragma unroll
  for(int s=0;s<STAGES-1;s++){ LOAD_STAGE(s,s); cp_commit(); }

  for(int kt=0;kt<KT;kt++){
    cp_wait<STAGES-2>();
    __syncthreads();
    int cs=kt%STAGES;
    uint32_t base=sb+cs*STAGE_B;
    if(kt+STAGES-1<KT) LOAD_STAGE(kt+STAGES-1,(kt+STAGES-1)%STAGES);
    cp_commit();
#pragma unroll
    for(int ks=0;ks<4;ks++){
      uint32_t a[2][4], b[4][4];
#pragma unroll
      for(int mt=0;mt<2;mt++){
        int row=arow+mt*16, c=ks*2+a_hi;
        ldm4(a[mt], base+row*128+((c^(row&7))<<4));
      }
#pragma unroll
      for(int p=0;p<4;p++){
        int row=brow+p*16, c=ks*2+b_hi;
        ldm4(b[p], base+A_ST+row*128+((c^(row&7))<<4));
      }
#pragma unroll
      for(int mt=0;mt<2;mt++)
#pragma unroll
        for(int nt=0;nt<8;nt++)
          mma16816(acc[mt][nt], a[mt], b[nt>>1]+(nt&1)*2);
    }
  }
  const int gid=L>>2, tig=L&3;
#pragma unroll
  for(int mt=0;mt<2;mt++)
#pragma unroll
    for(int nt=0;nt<8;nt++){
      int r0=m_base+wm*32+mt*16+gid;
      int c0=n_base+wn*64+nt*8+tig*2;
      float2 v0={acc[mt][nt][0],acc[mt][nt][1]};
      float2 v1={acc[mt][nt][2],acc[mt][nt][3]};
      *reinterpret_cast<float2*>(out+(size_t)r0*OUT_F+c0)=v0;
      *reinterpret_cast<float2*>(out+(size_t)(r0+8)*OUT_F+c0)=v1;
    }
#undef LOAD_STAGE
}

extern "C" void kernel_launch(void* const* d_in, const int* in_sizes, int n_in,
                              void* d_out, int out_size){
  const float* x      =(const float*)d_in[0];
  const void*  packed =d_in[1];
  const float* scales =(const float*)d_in[2];
  const void*  vals   =d_in[3];
  const int*   cols   =(const int*)d_in[4];
  const int*   ptr    =(const int*)d_in[5];
  const float* alpha  =(const float*)d_in[6];
  const int M = in_sizes[0]/IN_F;

  cudaFuncSetAttribute(k_gemm, cudaFuncAttributeMaxDynamicSharedMemorySize, SMEM_DYN);

  int nx_blocks = (M*IN_F/8)/256;
  k_pre<<<512+nx_blocks,256>>>(x, packed, scales, vals, cols, ptr, alpha);

  void *wp=nullptr,*xp=nullptr;
  cudaGetSymbolAddress(&wp,g_wh);
  cudaGetSymbolAddress(&xp,g_xh);
  dim3 grid(OUT_F/BN, M/BM);
  k_gemm<<<grid,256,SMEM_DYN>>>((const __half*)xp,(const __half*)wp,(float*)d_out);
}

// round 16
// speedup vs baseline: 1.1103x; 1.0172x over previous
#include <cuda_runtime.h>
#include <cuda_fp16.h>
#include <cuda_bf16.h>
#include <cstdint>

static constexpr int IN_F=4096, OUT_F=4096;
static constexpr int BM=128, BN=128, BK=64, STAGES=3;
static constexpr int A_ST=BM*BK*2, B_ST=BN*BK*2, STAGE_B=A_ST+B_ST;  // 32K
static constexpr int SMEM_DYN=STAGES*STAGE_B;                        // 98304

__device__ __align__(128) __half g_wh[(size_t)OUT_F*IN_F];
__device__ __align__(128) __half g_xh[(size_t)8192*IN_F];

#define DI __device__ __forceinline__
DI uint32_t s2u(const void* p){uint32_t a;
  asm("{ .reg .u64 t; cvta.to.shared.u64 t, %1; cvt.u32.u64 %0, t; }":"=r"(a):"l"(p));return a;}
DI void cpasync16(uint32_t d,const void* s){
  asm volatile("cp.async.cg.shared.global [%0], [%1], 16;"::"r"(d),"l"(s):"memory");}
DI void cp_commit(){asm volatile("cp.async.commit_group;":::"memory");}
template<int N> DI void cp_wait(){asm volatile("cp.async.wait_group %0;"::"n"(N):"memory");}
DI void ldm4(uint32_t* r,uint32_t a){
  asm volatile("ldmatrix.sync.aligned.m8n8.x4.shared.b16 {%0,%1,%2,%3}, [%4];"
    :"=r"(r[0]),"=r"(r[1]),"=r"(r[2]),"=r"(r[3]):"r"(a));}
DI void mma16816(float* d,const uint32_t* a,const uint32_t* b){
  asm volatile("mma.sync.aligned.m16n8k16.row.col.f32.f16.f16.f32 "
    "{%0,%1,%2,%3},{%4,%5,%6,%7},{%8,%9},{%0,%1,%2,%3};"
    :"+f"(d[0]),"+f"(d[1]),"+f"(d[2]),"+f"(d[3])
    :"r"(a[0]),"r"(a[1]),"r"(a[2]),"r"(a[3]),"r"(b[0]),"r"(b[1]));}

// ---- fused preprocessing: W dequant + CSR patch (blocks 0..511) and x->fp16 (rest)
__global__ void __launch_bounds__(256)
k_pre(const float* __restrict__ x, const void* __restrict__ pkv,
      const float* __restrict__ sc, const void* __restrict__ vv,
      const int* __restrict__ cols, const int* __restrict__ ptr,
      const float* __restrict__ alpha)
{
  const int tid=threadIdx.x, b=blockIdx.x;
  if(b < 512){
    __shared__ int s_mpk, s_mv;
    if(tid==0){
      const uint32_t* pk=(const uint32_t*)pkv;
      const uint32_t* vals=(const uint32_t*)vv;
      int lt=0, fl=0;
      for(int i=0;i<32;i++){uint32_t w=pk[i]; if(w<256u)lt++;
        uint32_t e=(w>>23)&0xFF; if(w==0u||(e>=126&&e<=135))fl++;}
      s_mpk=(fl>=30)?2:(lt>=30?1:0);
      int hb=0, lb=0, nz=0;
      for(int i=0;i<64;i++){uint32_t w=vals[i]; if(!w)continue; nz++;
        uint32_t eh=(w>>23)&0xFF, el=(w>>7)&0xFF;
        if(eh>=90&&eh<127)hb++; if(el>=90&&el<127)lb++;}
      s_mv=(nz&&lb*2>=nz)?1:((nz&&hb*2>=nz)?2:0);
    }
    __syncthreads();
    const int mpk=s_mpk, mv=s_mv;
    const int r0=b*8;
    constexpr int W32=IN_F/8;
#pragma unroll
    for(int j=0;j<16;j++){
      int idx=tid+j*256;
      int r=r0+(idx>>9), c=idx&(W32-1);
      uint32_t v;
      if(mpk==0) v=((const uint32_t*)pkv)[(size_t)r*W32+c];
      else if(mpk==1){const int32_t* p=(const int32_t*)pkv+(size_t)r*(IN_F/2)+c*4;
        v=(uint32_t)(p[0]&0xFF)|((uint32_t)(p[1]&0xFF)<<8)|
          ((uint32_t)(p[2]&0xFF)<<16)|((uint32_t)(p[3]&0xFF)<<24);}
      else {const float* p=(const float*)pkv+(size_t)r*(IN_F/2)+c*4;
        v=(uint32_t)(int)p[0]|((uint32_t)(int)p[1]<<8)|
          ((uint32_t)(int)p[2]<<16)|((uint32_t)(int)p[3]<<24);}
      float s=sc[r], f[8];
#pragma unroll
      for(int k=0;k<8;k++) f[k]=(float)((int)((v>>(4*k))&0xF)-8)*s;
      __half2 h0=__floats2half2_rn(f[0],f[1]), h1=__floats2half2_rn(f[2],f[3]);
      __half2 h2=__floats2half2_rn(f[4],f[5]), h3=__floats2half2_rn(f[6],f[7]);
      uint4 o={*(uint32_t*)&h0,*(uint32_t*)&h1,*(uint32_t*)&h2,*(uint32_t*)&h3};
      *reinterpret_cast<uint4*>(g_wh+(size_t)r*IN_F+(size_t)c*8)=o;
    }
    __syncthreads();
    {
      int r=r0+(tid>>5), lane=tid&31;
      float a=*alpha;
      int e=ptr[r+1];
      __half* w=g_wh+(size_t)r*IN_F;
      for(int j=ptr[r]+lane;j<e;j+=32){
        float v = (mv==0)? __half2float(((const __half*)vv)[j])
                : (mv==1)? __bfloat162float(((const __nv_bfloat16*)vv)[j])
                : ((const float*)vv)[j];
        int c=cols[j];
        w[c]=__float2half(__half2float(w[c])+a*v);
      }
    }
  } else {
    int i=(b-512)*256+tid;
    const float4* xp=(const float4*)x;
    float4 v0=xp[2*i], v1=xp[2*i+1];
    __half2 h0=__floats2half2_rn(v0.x,v0.y), h1=__floats2half2_rn(v0.z,v0.w);
    __half2 h2=__floats2half2_rn(v1.x,v1.y), h3=__floats2half2_rn(v1.z,v1.w);
    uint4 o={*(uint32_t*)&h0,*(uint32_t*)&h1,*(uint32_t*)&h2,*(uint32_t*)&h3};
    *reinterpret_cast<uint4*>(g_xh+(size_t)i*8)=o;
  }
}

// ---- GEMM: CTA 128x128 @256thr, warp 32x64, 3 stages, 2 CTAs/SM,
//      register double-buffered fragments (prefetch ks+1 under ks MMAs)
__global__ void __launch_bounds__(256, 2)
k_gemm(const __half* __restrict__ X, const __half* __restrict__ W, float* __restrict__ out){
  extern __shared__ char smem[];
  uint32_t sb=s2u(smem);
  const int tid=threadIdx.x, wid=tid>>5, L=tid&31;
  const int wm=wid>>1, wn=wid&1;                      // 4 x 2 warps
  const int m_base=blockIdx.y*BM, n_base=blockIdx.x*BN;
  const __half* gA=X+(size_t)m_base*IN_F;
  const __half* gW=W+(size_t)n_base*IN_F;
  const int arow=wm*32+(L&15), a_hi=L>>4;             // mt (0..1) adds 16
  const int brow=wn*64+(L>>4)*8+(L&7), b_hi=(L>>3)&1; // p (0..3) adds 16
  float acc[2][8][4];
#pragma unroll
  for(int mt=0;mt<2;mt++)
#pragma unroll
    for(int nt=0;nt<8;nt++)
#pragma unroll
      for(int q=0;q<4;q++) acc[mt][nt][q]=0.f;
  constexpr int KT=IN_F/BK;                           // 64

#define LOAD_STAGE(kt,s) do{ \
    uint32_t b_=sb+(s)*STAGE_B; \
    const __half* ga_=gA+(size_t)(kt)*BK; \
    const __half* gb_=gW+(size_t)(kt)*BK; \
    _Pragma("unroll") for(int i_=0;i_<4;i_++){ \
      int ix_=tid+i_*256, r_=ix_>>3, c_=ix_&7; \
      cpasync16(b_+r_*128+((c_^(r_&7))<<4), ga_+(size_t)r_*IN_F+c_*8);} \
    _Pragma("unroll") for(int i_=0;i_<4;i_++){ \
      int ix_=tid+i_*256, r_=ix_>>3, c_=ix_&7; \
      cpasync16(b_+A_ST+r_*128+((c_^(r_&7))<<4), gb_+(size_t)r_*IN_F+c_*8);} \
  }while(0)

#define LDFRAG(ks, buf) do{ \
    _Pragma("unroll") for(int mt_=0;mt_<2;mt_++){ \
      int row_=arow+mt_*16, c_=(ks)*2+a_hi; \
      ldm4(ua[buf][mt_], base+row_*128+((c_^(row_&7))<<4)); } \
    _Pragma("unroll") for(int p_=0;p_<4;p_++){ \
      int row_=brow+p_*16, c_=(ks)*2+b_hi; \
      ldm4(ub[buf][p_], base+A_ST+row_*128+((c_^(row_&7))<<4)); } \
  }while(0)

#pragma unroll
  for(int s=0;s<STAGES-1;s++){ LOAD_STAGE(s,s); cp_commit(); }

  for(int kt=0;kt<KT;kt++){
    cp_wait<STAGES-2>();
    __syncthreads();
    int cs=kt%STAGES;
    uint32_t base=sb+cs*STAGE_B;
    if(kt+STAGES-1<KT) LOAD_STAGE(kt+STAGES-1,(kt+STAGES-1)%STAGES);
    cp_commit();

    uint32_t ua[2][2][4], ub[2][4][4];
    LDFRAG(0, 0);
#pragma unroll
    for(int ks=0;ks<4;ks++){
      int cur=ks&1;
      if(ks<3) LDFRAG(ks+1, cur^1);
#pragma unroll
      for(int mt=0;mt<2;mt++)
#pragma unroll
        for(int nt=0;nt<8;nt++)
          mma16816(acc[mt][nt], ua[cur][mt], ub[cur][nt>>1]+(nt&1)*2);
    }
  }
  const int gid=L>>2, tig=L&3;
#pragma unroll
  for(int mt=0;mt<2;mt++)
#pragma unroll
    for(int nt=0;nt<8;nt++){
      int r0=m_base+wm*32+mt*16+gid;
      int c0=n_base+wn*64+nt*8+tig*2;
      float2 v0={acc[mt][nt][0],acc[mt][nt][1]};
      float2 v1={acc[mt][nt][2],acc[mt][nt][3]};
      *reinterpret_cast<float2*>(out+(size_t)r0*OUT_F+c0)=v0;
      *reinterpret_cast<float2*>(out+(size_t)(r0+8)*OUT_F+c0)=v1;
    }
#undef LOAD_STAGE
#undef LDFRAG
}

extern "C" void kernel_launch(void* const* d_in, const int* in_sizes, int n_in,
                              void* d_out, int out_size){
  const float* x      =(const float*)d_in[0];
  const void*  packed =d_in[1];
  const float* scales =(const float*)d_in[2];
  const void*  vals   =d_in[3];
  const int*   cols   =(const int*)d_in[4];
  const int*   ptr    =(const int*)d_in[5];
  const float* alpha  =(const float*)d_in[6];
  const int M = in_sizes[0]/IN_F;

  cudaFuncSetAttribute(k_gemm, cudaFuncAttributeMaxDynamicSharedMemorySize, SMEM_DYN);

  int nx_blocks = (M*IN_F/8)/256;
  k_pre<<<512+nx_blocks,256>>>(x, packed, scales, vals, cols, ptr, alpha);

  void *wp=nullptr,*xp=nullptr;
  cudaGetSymbolAddress(&wp,g_wh);
  cudaGetSymbolAddress(&xp,g_xh);
  dim3 grid(OUT_F/BN, M/BM);
  k_gemm<<<grid,256,SMEM_DYN>>>((const __half*)xp,(const __half*)wp,(float*)d_out);
}